// round 15
// baseline (speedup 1.0000x reference)
#include <cuda_runtime.h>
#include <cuda_bf16.h>
#include <math.h>
#include <stdint.h>

#define NMAX 100000
#define EMAX 1600000
#define MMAX 10000
#define DD   128
#define BN_EPS 1e-5f

// ---------------- scratch (device globals) ----------------
__device__ float g_t [NMAX * DD];
__device__ float g_z [NMAX * DD];
__device__ float g_w [NMAX * DD];
__device__ float g_h2[MMAX * DD];
__device__ float g_t2[MMAX * DD];
__device__ float g_z2[MMAX * DD];

__device__ int g_rp  [NMAX + 4];
__device__ int g_cur [NMAX];
__device__ int g_adj [EMAX];
__device__ int g_mask[NMAX];
__device__ int g_map [NMAX];
__device__ int g_sub [2 * EMAX];
__device__ int g_cnt [1];
__device__ int g_bsum[64];

// 8 stat regions: [0:128) sum, [128:256) sumsq
__device__ float g_stats[8][256];

// ---------------- helpers ----------------
__device__ __forceinline__ void mma_bf16(float* c, uint32_t a0, uint32_t a1,
                                         uint32_t a2, uint32_t a3,
                                         uint32_t b0, uint32_t b1) {
    asm volatile(
        "mma.sync.aligned.m16n8k16.row.col.f32.bf16.bf16.f32 "
        "{%0,%1,%2,%3}, {%4,%5,%6,%7}, {%8,%9}, {%0,%1,%2,%3};\n"
        : "+f"(c[0]), "+f"(c[1]), "+f"(c[2]), "+f"(c[3])
        : "r"(a0), "r"(a1), "r"(a2), "r"(a3), "r"(b0), "r"(b1));
}

__device__ __forceinline__ uint32_t pk_bf2(float e0, float e1) {
    __nv_bfloat162 t = __floats2bfloat162_rn(e0, e1);
    return *reinterpret_cast<uint32_t*>(&t);
}

// split float2 into bf16 hi word + bf16 lo (residual) word
__device__ __forceinline__ void split2(float e0, float e1, uint32_t& hw, uint32_t& lw) {
    __nv_bfloat16 h0 = __float2bfloat16(e0);
    __nv_bfloat16 h1 = __float2bfloat16(e1);
    float l0 = e0 - __bfloat162float(h0);
    float l1 = e1 - __bfloat162float(h1);
    __nv_bfloat162 hh; hh.x = h0; hh.y = h1;
    hw = *reinterpret_cast<uint32_t*>(&hh);
    lw = pk_bf2(l0, l1);
}

__device__ __forceinline__ void bnparam(const float* __restrict__ st,
                                        const float* __restrict__ g,
                                        const float* __restrict__ b,
                                        float inv, int c, float& sc, float& sh) {
    float m = st[c] * inv;
    float v = st[128 + c] * inv - m * m;
    sc = g[c] * rsqrtf(v + BN_EPS);
    sh = b[c] - m * sc;
}

// ---------------- init ----------------
__global__ void k_init(int* __restrict__ mask, int* __restrict__ cur,
                       int* __restrict__ cnt, float* __restrict__ stats,
                       float* __restrict__ out, int n) {
    int i = blockIdx.x * blockDim.x + threadIdx.x;
    if (i < n) { mask[i] = 0; cur[i] = 0; }
    if (i < 8 * 256) stats[i] = 0.f;
    if (i == 0) { *cnt = 0; *out = 0.f; }
}

__global__ void k_buildmaps(const int* __restrict__ mn, int* __restrict__ mask,
                            int* __restrict__ map, int m) {
    int i = blockIdx.x * blockDim.x + threadIdx.x;
    if (i >= m) return;
    int r = mn[i];
    mask[r] = 1;
    map[r]  = i;
}

__global__ void k_gatherfeat(const float* __restrict__ feat, const int* __restrict__ mn,
                             float* __restrict__ h2, int m4) {
    int i = blockIdx.x * blockDim.x + threadIdx.x;
    if (i >= m4) return;
    int row = i >> 5;
    int q   = i & 31;
    int r   = mn[row];
    ((float4*)h2)[i] = ((const float4*)feat)[(size_t)r * 32 + q];
}

// copy with optional bn+relu transform (per column)
__global__ void k_copyT(const float* __restrict__ src, float* __restrict__ dst, int n4,
                        const float* __restrict__ st, const float* __restrict__ gg,
                        const float* __restrict__ bb, int cnt) {
    int i = blockIdx.x * blockDim.x + threadIdx.x;
    if (i >= n4) return;
    float4 v = ((const float4*)src)[i];
    if (st) {
        int c = (i & 31) * 4;
        float inv = 1.f / (float)cnt;
        float sc, sh;
        bnparam(st, gg, bb, inv, c + 0, sc, sh); v.x = fmaxf(fmaf(v.x, sc, sh), 0.f);
        bnparam(st, gg, bb, inv, c + 1, sc, sh); v.y = fmaxf(fmaf(v.y, sc, sh), 0.f);
        bnparam(st, gg, bb, inv, c + 2, sc, sh); v.z = fmaxf(fmaf(v.z, sc, sh), 0.f);
        bnparam(st, gg, bb, inv, c + 3, sc, sh); v.w = fmaxf(fmaf(v.w, sc, sh), 0.f);
    }
    ((float4*)dst)[i] = v;
}

// ---------------- CSR build ----------------
__global__ void k_deg_sub(const int* __restrict__ src, const int* __restrict__ dst,
                          const int* __restrict__ mask, const int* __restrict__ map,
                          int* __restrict__ deg, int* __restrict__ sub,
                          int* __restrict__ cnt, int e) {
    int i = blockIdx.x * blockDim.x + threadIdx.x;
    if (i >= e) return;
    int s = src[i], d = dst[i];
    atomicAdd(&deg[d], 1);
    if (mask[s] && mask[d]) {
        int p = atomicAdd(cnt, 1);
        sub[2 * p]     = map[s];
        sub[2 * p + 1] = map[d];
    }
}

// ---- multi-block scan, phase A ----
__global__ void k_scanA(const int* __restrict__ deg, int* __restrict__ rp,
                        int* __restrict__ bsum, int n) {
    __shared__ int warpsum[32];
    int lane = threadIdx.x & 31, wid = threadIdx.x >> 5;
    int i0 = blockIdx.x * 4096 + threadIdx.x * 4;
    int4 v = make_int4(0, 0, 0, 0);
    if (i0 + 3 < n) {
        v = *(const int4*)(deg + i0);
    } else {
        if (i0     < n) v.x = deg[i0];
        if (i0 + 1 < n) v.y = deg[i0 + 1];
        if (i0 + 2 < n) v.z = deg[i0 + 2];
        if (i0 + 3 < n) v.w = deg[i0 + 3];
    }
    int t0 = v.x, t1 = t0 + v.y, t2 = t1 + v.z, t3 = t2 + v.w;
    int tsum = t3;
    int sc = tsum;
    #pragma unroll
    for (int off = 1; off < 32; off <<= 1) {
        int o = __shfl_up_sync(0xFFFFFFFFu, sc, off);
        if (lane >= off) sc += o;
    }
    if (lane == 31) warpsum[wid] = sc;
    __syncthreads();
    if (wid == 0) {
        int ws = warpsum[lane];
        #pragma unroll
        for (int off = 1; off < 32; off <<= 1) {
            int o = __shfl_up_sync(0xFFFFFFFFu, ws, off);
            if (lane >= off) ws += o;
        }
        warpsum[lane] = ws;
    }
    __syncthreads();
    int warpoff = (wid > 0) ? warpsum[wid - 1] : 0;
    int excl = warpoff + sc - tsum;
    if (i0     < n) rp[i0]     = excl;
    if (i0 + 1 < n) rp[i0 + 1] = excl + t0;
    if (i0 + 2 < n) rp[i0 + 2] = excl + t1;
    if (i0 + 3 < n) rp[i0 + 3] = excl + t2;
    if (threadIdx.x == 0) bsum[blockIdx.x] = warpsum[31];
}

// ---- phase C ----
__global__ void k_scanC(const int* __restrict__ bsum, int* __restrict__ rp,
                        int* __restrict__ cur, int n, int nb) {
    __shared__ int soff[33];
    if (threadIdx.x < 32) {
        int v = (threadIdx.x < nb) ? bsum[threadIdx.x] : 0;
        int incl = v;
        #pragma unroll
        for (int off = 1; off < 32; off <<= 1) {
            int o = __shfl_up_sync(0xFFFFFFFFu, incl, off);
            if ((threadIdx.x & 31) >= off) incl += o;
        }
        soff[threadIdx.x] = incl - v;
        if (threadIdx.x == 31) soff[32] = incl;
    }
    __syncthreads();
    int i = blockIdx.x * blockDim.x + threadIdx.x;
    int n4 = (n + 3) >> 2;
    if (i < n4) {
        int off = soff[(i >> 10)];
        int base = i * 4;
        if (base + 3 < n) {
            int4 v = *(int4*)(rp + base);
            v.x += off; v.y += off; v.z += off; v.w += off;
            *(int4*)(rp + base)  = v;
            *(int4*)(cur + base) = v;
        } else {
            for (int j = base; j < n; j++) {
                int v = rp[j] + off;
                rp[j] = v; cur[j] = v;
            }
        }
    }
    if (i == 0) rp[n] = soff[32];
}

__global__ void k_fill(const int* __restrict__ src, const int* __restrict__ dst,
                       int* __restrict__ cur, int* __restrict__ adj, int e) {
    int i = blockIdx.x * blockDim.x + threadIdx.x;
    if (i >= e) return;
    int d = dst[i];
    int p = atomicAdd(&cur[d], 1);
    adj[p] = src[i];
}

// ---------------- aggregation (warp-cooperative, row-range variants) ----------------
__device__ __forceinline__ float4 xf4(float4 v, float4 sc, float4 sh, bool tf) {
    if (tf) {
        v.x = fmaxf(fmaf(v.x, sc.x, sh.x), 0.f);
        v.y = fmaxf(fmaf(v.y, sc.y, sh.y), 0.f);
        v.z = fmaxf(fmaf(v.z, sc.z, sh.z), 0.f);
        v.w = fmaxf(fmaf(v.w, sc.w, sh.w), 0.f);
    }
    return v;
}

// layer-1 agg with fused mask-token selection over rows [rbase, rbase+nrows)
__global__ void k_agg_m(const float* __restrict__ feat, const float* __restrict__ token,
                        const int* __restrict__ mask, float* __restrict__ dst,
                        const int* __restrict__ rp, const int* __restrict__ adj,
                        int rbase, int nrows) {
    int w    = (blockIdx.x * blockDim.x + threadIdx.x) >> 5;
    int lane = threadIdx.x & 31;
    if (w >= nrows) return;
    int node = rbase + w;
    const float4* f4 = (const float4*)feat;
    float4 tok = __ldg(&((const float4*)token)[lane]);
    float4 acc = mask[node] ? tok : f4[(size_t)node * 32 + lane];
    int s = rp[node], e = rp[node + 1];
    int i = s;
    for (; i + 4 <= e; i += 4) {
        int u0 = adj[i], u1 = adj[i + 1], u2 = adj[i + 2], u3 = adj[i + 3];
        int m0 = mask[u0], m1 = mask[u1], m2 = mask[u2], m3 = mask[u3];
        float4 v0 = __ldg(&f4[(size_t)u0 * 32 + lane]);
        float4 v1 = __ldg(&f4[(size_t)u1 * 32 + lane]);
        float4 v2 = __ldg(&f4[(size_t)u2 * 32 + lane]);
        float4 v3 = __ldg(&f4[(size_t)u3 * 32 + lane]);
        if (m0) v0 = tok; if (m1) v1 = tok; if (m2) v2 = tok; if (m3) v3 = tok;
        acc.x += v0.x + v1.x + v2.x + v3.x;
        acc.y += v0.y + v1.y + v2.y + v3.y;
        acc.z += v0.z + v1.z + v2.z + v3.z;
        acc.w += v0.w + v1.w + v2.w + v3.w;
    }
    for (; i < e; i++) {
        int u = adj[i];
        float4 v = mask[u] ? tok : __ldg(&f4[(size_t)u * 32 + lane]);
        acc.x += v.x; acc.y += v.y; acc.z += v.z; acc.w += v.w;
    }
    ((float4*)dst)[(size_t)node * 32 + lane] = acc;
}

// bn-transform agg over rows [rbase, rbase+nrows) (gather reads ALL of src)
__global__ void k_agg(const float* __restrict__ src, float* __restrict__ dst,
                      const int* __restrict__ rp, const int* __restrict__ adj,
                      int rbase, int nrows,
                      const float* __restrict__ st, const float* __restrict__ gg,
                      const float* __restrict__ bb, int cnt) {
    int w    = (blockIdx.x * blockDim.x + threadIdx.x) >> 5;
    int lane = threadIdx.x & 31;
    if (w >= nrows) return;
    int node = rbase + w;
    bool tf = (st != nullptr);
    float4 sc = make_float4(1.f, 1.f, 1.f, 1.f), sh = make_float4(0.f, 0.f, 0.f, 0.f);
    if (tf) {
        float inv = 1.f / (float)cnt;
        int c = lane * 4;
        bnparam(st, gg, bb, inv, c + 0, sc.x, sh.x);
        bnparam(st, gg, bb, inv, c + 1, sc.y, sh.y);
        bnparam(st, gg, bb, inv, c + 2, sc.z, sh.z);
        bnparam(st, gg, bb, inv, c + 3, sc.w, sh.w);
    }
    const float4* s4 = (const float4*)src;
    float4 acc = xf4(s4[(size_t)node * 32 + lane], sc, sh, tf);
    int s = rp[node], e = rp[node + 1];
    int i = s;
    for (; i + 4 <= e; i += 4) {
        int u0 = adj[i], u1 = adj[i + 1], u2 = adj[i + 2], u3 = adj[i + 3];
        float4 v0 = __ldg(&s4[(size_t)u0 * 32 + lane]);
        float4 v1 = __ldg(&s4[(size_t)u1 * 32 + lane]);
        float4 v2 = __ldg(&s4[(size_t)u2 * 32 + lane]);
        float4 v3 = __ldg(&s4[(size_t)u3 * 32 + lane]);
        v0 = xf4(v0, sc, sh, tf); v1 = xf4(v1, sc, sh, tf);
        v2 = xf4(v2, sc, sh, tf); v3 = xf4(v3, sc, sh, tf);
        acc.x += v0.x + v1.x + v2.x + v3.x;
        acc.y += v0.y + v1.y + v2.y + v3.y;
        acc.z += v0.z + v1.z + v2.z + v3.z;
        acc.w += v0.w + v1.w + v2.w + v3.w;
    }
    for (; i < e; i++) {
        int u = adj[i];
        float4 v = xf4(__ldg(&s4[(size_t)u * 32 + lane]), sc, sh, tf);
        acc.x += v.x; acc.y += v.y; acc.z += v.z; acc.w += v.w;
    }
    ((float4*)dst)[(size_t)node * 32 + lane] = acc;
}

__global__ void k_subagg(const float* __restrict__ src, float* __restrict__ dst,
                         const int* __restrict__ sub, const int* __restrict__ cntp,
                         const float* __restrict__ st, const float* __restrict__ gg,
                         const float* __restrict__ bb, int cnt) {
    int nwarps = (gridDim.x * blockDim.x) >> 5;
    int w0     = (blockIdx.x * blockDim.x + threadIdx.x) >> 5;
    int lane   = threadIdx.x & 31;
    bool tf = (st != nullptr);
    float4 sc = make_float4(1.f, 1.f, 1.f, 1.f), sh = make_float4(0.f, 0.f, 0.f, 0.f);
    if (tf) {
        float inv = 1.f / (float)cnt;
        int c = lane * 4;
        bnparam(st, gg, bb, inv, c + 0, sc.x, sh.x);
        bnparam(st, gg, bb, inv, c + 1, sc.y, sh.y);
        bnparam(st, gg, bb, inv, c + 2, sc.z, sh.z);
        bnparam(st, gg, bb, inv, c + 3, sc.w, sh.w);
    }
    int c = *cntp;
    for (int e = w0; e < c; e += nwarps) {
        int s = sub[2 * e], d = sub[2 * e + 1];
        float4 v = xf4(((const float4*)src)[(size_t)s * 32 + lane], sc, sh, tf);
        float* tp = dst + (size_t)d * 128 + lane * 4;
        atomicAdd(tp + 0, v.x);
        atomicAdd(tp + 1, v.y);
        atomicAdd(tp + 2, v.z);
        atomicAdd(tp + 3, v.w);
    }
}

// ---------------- tensor-core GEMM (bf16 3-term split, ~fp32-accurate) ----------------
// 128-row tiles at r_off + blockIdx*128; single As buffer + register prefetch, 2 CTAs/SM.
#define GEMM_SMEM_BYTES 94208

__global__ __launch_bounds__(256, 2) void k_gemm_tc(
    const float* __restrict__ A, const float* __restrict__ W, float* __restrict__ C,
    int n, int r_off, const float* __restrict__ stats_in, const float* __restrict__ gg,
    const float* __restrict__ bb, int cnt, float* __restrict__ stats_out) {
    extern __shared__ uint32_t sm[];
    uint4* As   = (uint4*)sm;                          // [128][12]
    uint2* Wh   = (uint2*)((char*)sm + 24576);         // [32][132]
    uint2* Wl   = (uint2*)((char*)sm + 58368);
    float* bnsc = (float*)((char*)sm + 92160);
    float* bnsh = bnsc + 128;
    float* ssum = bnsh + 128;
    float* ssq  = ssum + 128;

    int tid = threadIdx.x;
    int r0  = r_off + blockIdx.x * 128;
    bool tf = (stats_in != nullptr);

    #pragma unroll 4
    for (int it = 0; it < 32; it++) {
        int idx = it * 256 + tid;
        int p = idx >> 7, nn = idx & 127;
        float v0 = W[(2 * p) * 128 + nn];
        float v1 = W[(2 * p + 1) * 128 + nn];
        uint32_t hw, lw;
        split2(v0, v1, hw, lw);
        int ktg = p >> 3, r = p & 7;
        int base = (ktg * 4 + (r & 3)) * 132 + nn;
        int slot = r >> 2;
        ((uint32_t*)&Wh[base])[slot] = hw;
        ((uint32_t*)&Wl[base])[slot] = lw;
    }
    if (tid < 128) {
        float s = 1.f, sh = 0.f;
        if (tf) {
            float inv = 1.f / (float)cnt;
            bnparam(stats_in, gg, bb, inv, tid, s, sh);
        }
        bnsc[tid] = s; bnsh[tid] = sh;
        ssum[tid] = 0.f; ssq[tid] = 0.f;
    }
    __syncthreads();

    int warp = tid >> 5, lane = tid & 31, g = lane >> 2, kq = lane & 3;
    int srow = tid >> 3, sq = tid & 7;
    int sktgl = sq >> 2, skqs = sq & 3;

    float2 va[4], vb[4];

    auto loadch = [&](int ch) {
        int kbase = ch * 32 + sktgl * 16 + skqs * 2;
        #pragma unroll
        for (int i = 0; i < 4; i++) {
            int gr = r0 + i * 32 + srow;
            if (gr < n) {
                va[i] = *(const float2*)(A + (size_t)gr * 128 + kbase);
                vb[i] = *(const float2*)(A + (size_t)gr * 128 + kbase + 8);
            } else {
                va[i] = make_float2(0.f, 0.f);
                vb[i] = make_float2(0.f, 0.f);
            }
        }
    };
    auto storech = [&](int ch) {
        int kbase = ch * 32 + sktgl * 16 + skqs * 2;
        float sc0 = bnsc[kbase + 0], sh0 = bnsh[kbase + 0];
        float sc1 = bnsc[kbase + 1], sh1 = bnsh[kbase + 1];
        float sc8 = bnsc[kbase + 8], sh8 = bnsh[kbase + 8];
        float sc9 = bnsc[kbase + 9], sh9 = bnsh[kbase + 9];
        #pragma unroll
        for (int i = 0; i < 4; i++) {
            int row = i * 32 + srow;
            float2 a = va[i], b = vb[i];
            if (tf) {
                a.x = fmaxf(fmaf(a.x, sc0, sh0), 0.f);
                a.y = fmaxf(fmaf(a.y, sc1, sh1), 0.f);
                b.x = fmaxf(fmaf(b.x, sc8, sh8), 0.f);
                b.y = fmaxf(fmaf(b.y, sc9, sh9), 0.f);
            }
            uint32_t ha, la, hb, lb;
            split2(a.x, a.y, ha, la);
            split2(b.x, b.y, hb, lb);
            As[row * 12 + sq] = make_uint4(ha, hb, la, lb);
        }
    };

    float acc[16][4];
    #pragma unroll
    for (int nt = 0; nt < 16; nt++)
        #pragma unroll
        for (int j = 0; j < 4; j++) acc[nt][j] = 0.f;

    loadch(0);
    storech(0);
    __syncthreads();

    for (int ch = 0; ch < 4; ch++) {
        if (ch < 3) loadch(ch + 1);
        #pragma unroll
        for (int ktgl = 0; ktgl < 2; ktgl++) {
            int q0 = ktgl * 4 + kq;
            int arow = warp * 16 + g;
            uint4 A0 = As[(arow)     * 12 + q0];
            uint4 A1 = As[(arow + 8) * 12 + q0];
            int ktgG = ch * 2 + ktgl;
            const uint2* whp = Wh + (ktgG * 4 + kq) * 132;
            const uint2* wlp = Wl + (ktgG * 4 + kq) * 132;
            #pragma unroll
            for (int nt = 0; nt < 16; nt++) {
                int nn = nt * 8 + g;
                uint2 bh = whp[nn];
                uint2 bl = wlp[nn];
                mma_bf16(acc[nt], A0.x, A1.x, A0.y, A1.y, bh.x, bh.y);
                mma_bf16(acc[nt], A0.z, A1.z, A0.w, A1.w, bh.x, bh.y);
                mma_bf16(acc[nt], A0.x, A1.x, A0.y, A1.y, bl.x, bl.y);
            }
        }
        __syncthreads();
        if (ch < 3) {
            storech(ch + 1);
            __syncthreads();
        }
    }

    int rA = r0 + warp * 16 + g;
    int rB = rA + 8;
    bool okA = rA < n, okB = rB < n;
    #pragma unroll
    for (int nt = 0; nt < 16; nt++) {
        float* a = acc[nt];
        int col = nt * 8 + kq * 2;
        if (okA) *(float2*)(C + (size_t)rA * 128 + col) = make_float2(a[0], a[1]);
        if (okB) *(float2*)(C + (size_t)rB * 128 + col) = make_float2(a[2], a[3]);
    }
    #pragma unroll
    for (int nt = 0; nt < 16; nt++) {
        float* a = acc[nt];
        float s0 = 0.f, s1 = 0.f, q0 = 0.f, q1 = 0.f;
        if (okA) { s0 += a[0]; q0 += a[0] * a[0]; s1 += a[1]; q1 += a[1] * a[1]; }
        if (okB) { s0 += a[2]; q0 += a[2] * a[2]; s1 += a[3]; q1 += a[3] * a[3]; }
        #pragma unroll
        for (int o = 4; o < 32; o <<= 1) {
            s0 += __shfl_xor_sync(0xFFFFFFFFu, s0, o);
            s1 += __shfl_xor_sync(0xFFFFFFFFu, s1, o);
            q0 += __shfl_xor_sync(0xFFFFFFFFu, q0, o);
            q1 += __shfl_xor_sync(0xFFFFFFFFu, q1, o);
        }
        if (lane < 4) {
            int col = nt * 8 + lane * 2;
            atomicAdd(&ssum[col],     s0);
            atomicAdd(&ssum[col + 1], s1);
            atomicAdd(&ssq[col],      q0);
            atomicAdd(&ssq[col + 1],  q1);
        }
    }
    __syncthreads();
    if (tid < 128) {
        atomicAdd(&stats_out[tid],       ssum[tid]);
        atomicAdd(&stats_out[128 + tid], ssq[tid]);
    }
}

// ---------------- loss ----------------
__global__ void k_loss(const float* __restrict__ zon, const float* __restrict__ ztg,
                       const int* __restrict__ mn, int m,
                       const float* __restrict__ stO, const float* __restrict__ gO,
                       const float* __restrict__ bO, int cntO,
                       const float* __restrict__ stT, const float* __restrict__ gT,
                       const float* __restrict__ bT, int cntT,
                       float* __restrict__ out) {
    int gw   = (blockIdx.x * blockDim.x + threadIdx.x) >> 5;
    int lane = threadIdx.x & 31;
    __shared__ float ps[8];
    float val = 0.f;
    if (gw < m) {
        int c = lane * 4;
        float invO = 1.f / (float)cntO, invT = 1.f / (float)cntT;
        float4 scO, shO, scT, shT;
        bnparam(stO, gO, bO, invO, c + 0, scO.x, shO.x);
        bnparam(stO, gO, bO, invO, c + 1, scO.y, shO.y);
        bnparam(stO, gO, bO, invO, c + 2, scO.z, shO.z);
        bnparam(stO, gO, bO, invO, c + 3, scO.w, shO.w);
        bnparam(stT, gT, bT, invT, c + 0, scT.x, shT.x);
        bnparam(stT, gT, bT, invT, c + 1, scT.y, shT.y);
        bnparam(stT, gT, bT, invT, c + 2, scT.z, shT.z);
        bnparam(stT, gT, bT, invT, c + 3, scT.w, shT.w);
        int r = mn[gw];
        float4 x = ((const float4*)zon)[(size_t)r * 32 + lane];
        x = xf4(x, scO, shO, true);
        float4 y = ((const float4*)ztg)[(size_t)gw * 32 + lane];
        y = xf4(y, scT, shT, true);
        float dot = x.x * y.x + x.y * y.y + x.z * y.z + x.w * y.w;
        float nx  = x.x * x.x + x.y * x.y + x.z * x.z + x.w * x.w;
        float ny  = y.x * y.x + y.y * y.y + y.z * y.z + y.w * y.w;
        #pragma unroll
        for (int off = 16; off > 0; off >>= 1) {
            dot += __shfl_xor_sync(0xFFFFFFFFu, dot, off);
            nx  += __shfl_xor_sync(0xFFFFFFFFu, nx,  off);
            ny  += __shfl_xor_sync(0xFFFFFFFFu, ny,  off);
        }
        if (lane == 0) {
            float den = fmaxf(sqrtf(nx), 1e-12f) * fmaxf(sqrtf(ny), 1e-12f);
            val = (1.f - dot / den) / (float)m;
        }
    }
    int w = threadIdx.x >> 5;
    if (lane == 0) ps[w] = val;
    __syncthreads();
    if (threadIdx.x == 0) {
        float s = 0.f;
        #pragma unroll
        for (int i = 0; i < 8; i++) s += ps[i];
        atomicAdd(out, s);
    }
}

// ---------------- host orchestration ----------------
extern "C" void kernel_launch(void* const* d_in, const int* in_sizes, int n_in,
                              void* d_out, int out_size) {
    const float* feat  = (const float*)d_in[0];
    const float* token = (const float*)d_in[1];
    const int*   edge  = (const int*)d_in[2];
    const int*   mn    = (const int*)d_in[3];
    const float* onW1 = (const float*)d_in[4];
    const float* onW2 = (const float*)d_in[5];
    const float* ong1 = (const float*)d_in[6];
    const float* onb1 = (const float*)d_in[7];
    const float* ong2 = (const float*)d_in[8];
    const float* onb2 = (const float*)d_in[9];
    const float* tgW1 = (const float*)d_in[10];
    const float* tgW2 = (const float*)d_in[11];
    const float* tgg1 = (const float*)d_in[12];
    const float* tgb1 = (const float*)d_in[13];
    const float* tgg2 = (const float*)d_in[14];
    const float* tgb2 = (const float*)d_in[15];

    const int N = in_sizes[0] / DD;
    const int E = in_sizes[2] / 2;
    const int M = in_sizes[3];
    const int* srcp = edge;
    const int* dstp = edge + E;

    float *p_t, *p_z, *p_w, *p_h2, *p_t2, *p_z2;
    int *p_rp, *p_cur, *p_adj, *p_mask, *p_map, *p_sub, *p_cnt, *p_bsum;
    float* p_stats;
    cudaGetSymbolAddress((void**)&p_t, g_t);
    cudaGetSymbolAddress((void**)&p_z, g_z);
    cudaGetSymbolAddress((void**)&p_w, g_w);
    cudaGetSymbolAddress((void**)&p_h2, g_h2);
    cudaGetSymbolAddress((void**)&p_t2, g_t2);
    cudaGetSymbolAddress((void**)&p_z2, g_z2);
    cudaGetSymbolAddress((void**)&p_rp, g_rp);
    cudaGetSymbolAddress((void**)&p_cur, g_cur);
    cudaGetSymbolAddress((void**)&p_adj, g_adj);
    cudaGetSymbolAddress((void**)&p_mask, g_mask);
    cudaGetSymbolAddress((void**)&p_map, g_map);
    cudaGetSymbolAddress((void**)&p_sub, g_sub);
    cudaGetSymbolAddress((void**)&p_cnt, g_cnt);
    cudaGetSymbolAddress((void**)&p_bsum, g_bsum);
    cudaGetSymbolAddress((void**)&p_stats, g_stats);

    static cudaStream_t s1 = nullptr, s2 = nullptr;
    static cudaEvent_t evFork = nullptr, evJoin = nullptr;
    static cudaEvent_t evH0 = nullptr, evM1 = nullptr;
    static cudaEvent_t evB0 = nullptr, evA1 = nullptr;
    static bool init_done = false;
    if (!init_done) {
        cudaFuncSetAttribute(k_gemm_tc, cudaFuncAttributeMaxDynamicSharedMemorySize,
                             GEMM_SMEM_BYTES);
        cudaStreamCreateWithFlags(&s1, cudaStreamNonBlocking);
        cudaStreamCreateWithFlags(&s2, cudaStreamNonBlocking);
        cudaEventCreateWithFlags(&evFork, cudaEventDisableTiming);
        cudaEventCreateWithFlags(&evJoin, cudaEventDisableTiming);
        cudaEventCreateWithFlags(&evH0, cudaEventDisableTiming);
        cudaEventCreateWithFlags(&evM1, cudaEventDisableTiming);
        cudaEventCreateWithFlags(&evB0, cudaEventDisableTiming);
        cudaEventCreateWithFlags(&evA1, cudaEventDisableTiming);
        init_done = true;
    }

    cudaStream_t st = 0;
    const int TB = 256;
    const int n4M = M * 32;

    float* S0 = p_stats + 0 * 256;
    float* S1 = p_stats + 1 * 256;
    float* S2 = p_stats + 2 * 256;
    float* S3 = p_stats + 3 * 256;
    float* S4 = p_stats + 4 * 256;
    float* S5 = p_stats + 5 * 256;
    float* S6 = p_stats + 6 * 256;
    float* S7 = p_stats + 7 * 256;

    // row halves (H0 multiple of 128)
    const int H0 = ((N / 2 + 127) / 128) * 128;
    const int H1 = N - H0;
    const int g0 = H0 / 128, g1 = (H1 + 127) / 128;
    const int gM = (M + 127) / 128;
    const int nb = (N + 4095) / 4096;
    const int aggB0 = (H0 * 32 + TB - 1) / TB;
    const int aggB1 = (H1 * 32 + TB - 1) / TB;

    // ---- setup on st ----
    k_init<<<(N + TB - 1) / TB, TB, 0, st>>>(p_mask, p_cur, p_cnt, p_stats,
                                             (float*)d_out, N);
    k_buildmaps<<<(M + TB - 1) / TB, TB, 0, st>>>(mn, p_mask, p_map, M);
    k_deg_sub<<<(E + TB - 1) / TB, TB, 0, st>>>(srcp, dstp, p_mask, p_map,
                                                p_cur, p_sub, p_cnt, E);
    cudaEventRecord(evFork, st);

    // ---- CSR on st ----
    k_scanA<<<nb, 1024, 0, st>>>(p_cur, p_rp, p_bsum, N);
    k_scanC<<<((N + 3) / 4 + TB - 1) / TB, TB, 0, st>>>(p_bsum, p_rp, p_cur, N, nb);
    k_fill<<<(E + TB - 1) / TB, TB, 0, st>>>(srcp, dstp, p_cur, p_adj, E);

    // ---- L1: pipelined agg_m/gemm1 (agg_m reads feat; gemm1 writes z -> no alias) ----
    k_agg_m<<<aggB0, TB, 0, st>>>(feat, token, p_mask, p_t, p_rp, p_adj, 0, H0);
    cudaEventRecord(evH0, st);
    cudaStreamWaitEvent(s2, evH0, 0);
    k_agg_m<<<aggB1, TB, 0, s2>>>(feat, token, p_mask, p_t, p_rp, p_adj, H0, H1);
    cudaEventRecord(evM1, s2);
    k_gemm_tc<<<g0, 256, GEMM_SMEM_BYTES, st>>>(p_t, onW1, p_z, N, 0,
                                                nullptr, nullptr, nullptr, 0, S0);
    cudaStreamWaitEvent(st, evM1, 0);
    k_gemm_tc<<<g1, 256, GEMM_SMEM_BYTES, st>>>(p_t, onW1, p_z, N, H0,
                                                nullptr, nullptr, nullptr, 0, S0);
    // gemm2 (needs full S0): z -> z in-place (tile-local, safe)
    k_gemm_tc<<<g0 + g1, 256, GEMM_SMEM_BYTES, st>>>(p_z, onW2, p_z, N, 0,
                                                     S0, ong1, onb1, N, S1);

    // ---- L2: pipelined agg/gemm3 via separate w buffer (z stays read-only) ----
    k_agg<<<aggB0, TB, 0, st>>>(p_z, p_t, p_rp, p_adj, 0, H0,
                                S1, ong2, onb2, N);
    cudaEventRecord(evB0, st);
    cudaStreamWaitEvent(s2, evB0, 0);
    k_agg<<<aggB1, TB, 0, s2>>>(p_z, p_t, p_rp, p_adj, H0, H1,
                                S1, ong2, onb2, N);
    cudaEventRecord(evA1, s2);
    k_gemm_tc<<<g0, 256, GEMM_SMEM_BYTES, st>>>(p_t, onW1 + DD * DD, p_w, N, 0,
                                                nullptr, nullptr, nullptr, 0, S2);
    cudaStreamWaitEvent(st, evA1, 0);
    k_gemm_tc<<<g1, 256, GEMM_SMEM_BYTES, st>>>(p_t, onW1 + DD * DD, p_w, N, H0,
                                                nullptr, nullptr, nullptr, 0, S2);
    // gemm4 (needs full S2): w -> z
    k_gemm_tc<<<g0 + g1, 256, GEMM_SMEM_BYTES, st>>>(p_w, onW2 + DD * DD, p_z, N, 0,
                                                     S2, ong1 + DD, onb1 + DD, N, S3);

    // ---- target encoder (induced subgraph) on s1, overlapped ----
    cudaStreamWaitEvent(s1, evFork, 0);
    k_gatherfeat<<<(n4M + TB - 1) / TB, TB, 0, s1>>>(feat, mn, p_h2, n4M);
    k_copyT<<<(n4M + TB - 1) / TB, TB, 0, s1>>>(p_h2, p_t2, n4M,
                                                nullptr, nullptr, nullptr, 0);
    k_subagg<<<64, 256, 0, s1>>>(p_h2, p_t2, p_sub, p_cnt,
                                 nullptr, nullptr, nullptr, 0);
    k_gemm_tc<<<gM, 256, GEMM_SMEM_BYTES, s1>>>(p_t2, tgW1, p_z2, M, 0,
                                                nullptr, nullptr, nullptr, 0, S4);
    k_gemm_tc<<<gM, 256, GEMM_SMEM_BYTES, s1>>>(p_z2, tgW2, p_z2, M, 0,
                                                S4, tgg1, tgb1, M, S5);
    k_copyT<<<(n4M + TB - 1) / TB, TB, 0, s1>>>(p_z2, p_t2, n4M,
                                                S5, tgg2, tgb2, M);
    k_subagg<<<64, 256, 0, s1>>>(p_z2, p_t2, p_sub, p_cnt,
                                 S5, tgg2, tgb2, M);
    k_gemm_tc<<<gM, 256, GEMM_SMEM_BYTES, s1>>>(p_t2, tgW1 + DD * DD, p_z2, M, 0,
                                                nullptr, nullptr, nullptr, 0, S6);
    k_gemm_tc<<<gM, 256, GEMM_SMEM_BYTES, s1>>>(p_z2, tgW2 + DD * DD, p_z2, M, 0,
                                                S6, tgg1 + DD, tgb1 + DD, M, S7);
    cudaEventRecord(evJoin, s1);

    // ---- join + loss ----
    cudaStreamWaitEvent(st, evJoin, 0);
    k_loss<<<(M * 32 + TB - 1) / TB, TB, 0, st>>>(p_z, p_z2, mn, M,
                                                  S3, ong2 + DD, onb2 + DD, N,
                                                  S7, tgg2 + DD, tgb2 + DD, M,
                                                  (float*)d_out);
}

// round 17
// speedup vs baseline: 1.0737x; 1.0737x over previous
#include <cuda_runtime.h>
#include <cuda_bf16.h>
#include <math.h>
#include <stdint.h>

#define NMAX 100000
#define EMAX 1600000
#define MMAX 10000
#define DD   128
#define BN_EPS 1e-5f

// ---------------- scratch (device globals) ----------------
__device__ float g_t [NMAX * DD];
__device__ float g_z [NMAX * DD];
__device__ float g_h2[MMAX * DD];
__device__ float g_t2[MMAX * DD];
__device__ float g_z2[MMAX * DD];

__device__ int g_rp  [NMAX + 4];
__device__ int g_cur [NMAX];
__device__ int g_adj [EMAX];
__device__ int g_mask[NMAX];
__device__ int g_map [NMAX];
__device__ int g_sub [2 * EMAX];
__device__ int g_cnt [1];
__device__ int g_bsum[64];

// 8 stat regions: [0:128) sum, [128:256) sumsq
__device__ float g_stats[8][256];

// pre-split weights: 8 matrices x (hi,lo) x 4224 uint2 (the exact smem layout)
#define WSP_WORDS 4224
__device__ uint2 g_wsplit[8 * 2 * WSP_WORDS];

// ---------------- helpers ----------------
__device__ __forceinline__ void mma_bf16(float* c, uint32_t a0, uint32_t a1,
                                         uint32_t a2, uint32_t a3,
                                         uint32_t b0, uint32_t b1) {
    asm volatile(
        "mma.sync.aligned.m16n8k16.row.col.f32.bf16.bf16.f32 "
        "{%0,%1,%2,%3}, {%4,%5,%6,%7}, {%8,%9}, {%0,%1,%2,%3};\n"
        : "+f"(c[0]), "+f"(c[1]), "+f"(c[2]), "+f"(c[3])
        : "r"(a0), "r"(a1), "r"(a2), "r"(a3), "r"(b0), "r"(b1));
}

__device__ __forceinline__ uint32_t pk_bf2(float e0, float e1) {
    __nv_bfloat162 t = __floats2bfloat162_rn(e0, e1);
    return *reinterpret_cast<uint32_t*>(&t);
}

// split float2 into bf16 hi word + bf16 lo (residual) word
__device__ __forceinline__ void split2(float e0, float e1, uint32_t& hw, uint32_t& lw) {
    __nv_bfloat16 h0 = __float2bfloat16(e0);
    __nv_bfloat16 h1 = __float2bfloat16(e1);
    float l0 = e0 - __bfloat162float(h0);
    float l1 = e1 - __bfloat162float(h1);
    __nv_bfloat162 hh; hh.x = h0; hh.y = h1;
    hw = *reinterpret_cast<uint32_t*>(&hh);
    lw = pk_bf2(l0, l1);
}

__device__ __forceinline__ void bnparam(const float* __restrict__ st,
                                        const float* __restrict__ g,
                                        const float* __restrict__ b,
                                        float inv, int c, float& sc, float& sh) {
    float m = st[c] * inv;
    float v = st[128 + c] * inv - m * m;
    sc = g[c] * rsqrtf(v + BN_EPS);
    sh = b[c] - m * sc;
}

// ---------------- init ----------------
__global__ void k_init(int* __restrict__ mask, int* __restrict__ cur,
                       int* __restrict__ cnt, float* __restrict__ stats,
                       float* __restrict__ out, int n) {
    int i = blockIdx.x * blockDim.x + threadIdx.x;
    if (i < n) { mask[i] = 0; cur[i] = 0; }
    if (i < 8 * 256) stats[i] = 0.f;
    if (i == 0) { *cnt = 0; *out = 0.f; }
}

__global__ void k_buildmaps(const int* __restrict__ mn, int* __restrict__ mask,
                            int* __restrict__ map, int m) {
    int i = blockIdx.x * blockDim.x + threadIdx.x;
    if (i >= m) return;
    int r = mn[i];
    mask[r] = 1;
    map[r]  = i;
}

// ---------------- pre-split 8 weight matrices into the smem layout ----------------
__global__ void k_splitW(const float* __restrict__ W0, const float* __restrict__ W1,
                         const float* __restrict__ W2, const float* __restrict__ W3,
                         const float* __restrict__ W4, const float* __restrict__ W5,
                         const float* __restrict__ W6, const float* __restrict__ W7,
                         uint2* __restrict__ out) {
    int m = blockIdx.x;
    const float* W;
    switch (m) {
        case 0: W = W0; break;
        case 1: W = W1; break;
        case 2: W = W2; break;
        case 3: W = W3; break;
        case 4: W = W4; break;
        case 5: W = W5; break;
        case 6: W = W6; break;
        default: W = W7; break;
    }
    uint2* Wh = out + (size_t)m * 2 * WSP_WORDS;
    uint2* Wl = Wh + WSP_WORDS;
    int tid = threadIdx.x;
    #pragma unroll 4
    for (int it = 0; it < 32; it++) {
        int idx = it * 256 + tid;       // pair-major: p in [0,64), nn in [0,128)
        int p = idx >> 7, nn = idx & 127;
        float v0 = W[(2 * p) * 128 + nn];
        float v1 = W[(2 * p + 1) * 128 + nn];
        uint32_t hw, lw;
        split2(v0, v1, hw, lw);
        int ktg = p >> 3, r = p & 7;
        int base = (ktg * 4 + (r & 3)) * 132 + nn;
        int slot = r >> 2;
        ((uint32_t*)&Wh[base])[slot] = hw;
        ((uint32_t*)&Wl[base])[slot] = lw;
    }
}

__global__ void k_gatherfeat(const float* __restrict__ feat, const int* __restrict__ mn,
                             float* __restrict__ h2, int m4) {
    int i = blockIdx.x * blockDim.x + threadIdx.x;
    if (i >= m4) return;
    int row = i >> 5;
    int q   = i & 31;
    int r   = mn[row];
    ((float4*)h2)[i] = ((const float4*)feat)[(size_t)r * 32 + q];
}

// copy with optional bn+relu transform (per column)
__global__ void k_copyT(const float* __restrict__ src, float* __restrict__ dst, int n4,
                        const float* __restrict__ st, const float* __restrict__ gg,
                        const float* __restrict__ bb, int cnt) {
    int i = blockIdx.x * blockDim.x + threadIdx.x;
    if (i >= n4) return;
    float4 v = ((const float4*)src)[i];
    if (st) {
        int c = (i & 31) * 4;
        float inv = 1.f / (float)cnt;
        float sc, sh;
        bnparam(st, gg, bb, inv, c + 0, sc, sh); v.x = fmaxf(fmaf(v.x, sc, sh), 0.f);
        bnparam(st, gg, bb, inv, c + 1, sc, sh); v.y = fmaxf(fmaf(v.y, sc, sh), 0.f);
        bnparam(st, gg, bb, inv, c + 2, sc, sh); v.z = fmaxf(fmaf(v.z, sc, sh), 0.f);
        bnparam(st, gg, bb, inv, c + 3, sc, sh); v.w = fmaxf(fmaf(v.w, sc, sh), 0.f);
    }
    ((float4*)dst)[i] = v;
}

// ---------------- CSR build ----------------
__global__ void k_deg_sub(const int* __restrict__ src, const int* __restrict__ dst,
                          const int* __restrict__ mask, const int* __restrict__ map,
                          int* __restrict__ deg, int* __restrict__ sub,
                          int* __restrict__ cnt, int e) {
    int i = blockIdx.x * blockDim.x + threadIdx.x;
    if (i >= e) return;
    int s = src[i], d = dst[i];
    atomicAdd(&deg[d], 1);
    if (mask[s] && mask[d]) {
        int p = atomicAdd(cnt, 1);
        sub[2 * p]     = map[s];
        sub[2 * p + 1] = map[d];
    }
}

// ---- multi-block scan, phase A ----
__global__ void k_scanA(const int* __restrict__ deg, int* __restrict__ rp,
                        int* __restrict__ bsum, int n) {
    __shared__ int warpsum[32];
    int lane = threadIdx.x & 31, wid = threadIdx.x >> 5;
    int i0 = blockIdx.x * 4096 + threadIdx.x * 4;
    int4 v = make_int4(0, 0, 0, 0);
    if (i0 + 3 < n) {
        v = *(const int4*)(deg + i0);
    } else {
        if (i0     < n) v.x = deg[i0];
        if (i0 + 1 < n) v.y = deg[i0 + 1];
        if (i0 + 2 < n) v.z = deg[i0 + 2];
        if (i0 + 3 < n) v.w = deg[i0 + 3];
    }
    int t0 = v.x, t1 = t0 + v.y, t2 = t1 + v.z, t3 = t2 + v.w;
    int tsum = t3;
    int sc = tsum;
    #pragma unroll
    for (int off = 1; off < 32; off <<= 1) {
        int o = __shfl_up_sync(0xFFFFFFFFu, sc, off);
        if (lane >= off) sc += o;
    }
    if (lane == 31) warpsum[wid] = sc;
    __syncthreads();
    if (wid == 0) {
        int ws = warpsum[lane];
        #pragma unroll
        for (int off = 1; off < 32; off <<= 1) {
            int o = __shfl_up_sync(0xFFFFFFFFu, ws, off);
            if (lane >= off) ws += o;
        }
        warpsum[lane] = ws;
    }
    __syncthreads();
    int warpoff = (wid > 0) ? warpsum[wid - 1] : 0;
    int excl = warpoff + sc - tsum;
    if (i0     < n) rp[i0]     = excl;
    if (i0 + 1 < n) rp[i0 + 1] = excl + t0;
    if (i0 + 2 < n) rp[i0 + 2] = excl + t1;
    if (i0 + 3 < n) rp[i0 + 3] = excl + t2;
    if (threadIdx.x == 0) bsum[blockIdx.x] = warpsum[31];
}

// ---- phase C ----
__global__ void k_scanC(const int* __restrict__ bsum, int* __restrict__ rp,
                        int* __restrict__ cur, int n, int nb) {
    __shared__ int soff[33];
    if (threadIdx.x < 32) {
        int v = (threadIdx.x < nb) ? bsum[threadIdx.x] : 0;
        int incl = v;
        #pragma unroll
        for (int off = 1; off < 32; off <<= 1) {
            int o = __shfl_up_sync(0xFFFFFFFFu, incl, off);
            if ((threadIdx.x & 31) >= off) incl += o;
        }
        soff[threadIdx.x] = incl - v;
        if (threadIdx.x == 31) soff[32] = incl;
    }
    __syncthreads();
    int i = blockIdx.x * blockDim.x + threadIdx.x;
    int n4 = (n + 3) >> 2;
    if (i < n4) {
        int off = soff[(i >> 10)];
        int base = i * 4;
        if (base + 3 < n) {
            int4 v = *(int4*)(rp + base);
            v.x += off; v.y += off; v.z += off; v.w += off;
            *(int4*)(rp + base)  = v;
            *(int4*)(cur + base) = v;
        } else {
            for (int j = base; j < n; j++) {
                int v = rp[j] + off;
                rp[j] = v; cur[j] = v;
            }
        }
    }
    if (i == 0) rp[n] = soff[32];
}

__global__ void k_fill(const int* __restrict__ src, const int* __restrict__ dst,
                       int* __restrict__ cur, int* __restrict__ adj, int e) {
    int i = blockIdx.x * blockDim.x + threadIdx.x;
    if (i >= e) return;
    int d = dst[i];
    int p = atomicAdd(&cur[d], 1);
    adj[p] = src[i];
}

// ---------------- aggregation (warp-cooperative) ----------------
__device__ __forceinline__ float4 xf4(float4 v, float4 sc, float4 sh, bool tf) {
    if (tf) {
        v.x = fmaxf(fmaf(v.x, sc.x, sh.x), 0.f);
        v.y = fmaxf(fmaf(v.y, sc.y, sh.y), 0.f);
        v.z = fmaxf(fmaf(v.z, sc.z, sh.z), 0.f);
        v.w = fmaxf(fmaf(v.w, sc.w, sh.w), 0.f);
    }
    return v;
}

// layer-1 agg with fused mask-token selection
__global__ void k_agg_m(const float* __restrict__ feat, const float* __restrict__ token,
                        const int* __restrict__ mask, float* __restrict__ dst,
                        const int* __restrict__ rp, const int* __restrict__ adj, int n) {
    int w    = (blockIdx.x * blockDim.x + threadIdx.x) >> 5;
    int lane = threadIdx.x & 31;
    if (w >= n) return;
    const float4* f4 = (const float4*)feat;
    float4 tok = __ldg(&((const float4*)token)[lane]);
    float4 acc = mask[w] ? tok : f4[(size_t)w * 32 + lane];
    int s = rp[w], e = rp[w + 1];
    int i = s;
    for (; i + 4 <= e; i += 4) {
        int u0 = adj[i], u1 = adj[i + 1], u2 = adj[i + 2], u3 = adj[i + 3];
        int m0 = mask[u0], m1 = mask[u1], m2 = mask[u2], m3 = mask[u3];
        float4 v0 = __ldg(&f4[(size_t)u0 * 32 + lane]);
        float4 v1 = __ldg(&f4[(size_t)u1 * 32 + lane]);
        float4 v2 = __ldg(&f4[(size_t)u2 * 32 + lane]);
        float4 v3 = __ldg(&f4[(size_t)u3 * 32 + lane]);
        if (m0) v0 = tok; if (m1) v1 = tok; if (m2) v2 = tok; if (m3) v3 = tok;
        acc.x += v0.x + v1.x + v2.x + v3.x;
        acc.y += v0.y + v1.y + v2.y + v3.y;
        acc.z += v0.z + v1.z + v2.z + v3.z;
        acc.w += v0.w + v1.w + v2.w + v3.w;
    }
    for (; i < e; i++) {
        int u = adj[i];
        float4 v = mask[u] ? tok : __ldg(&f4[(size_t)u * 32 + lane]);
        acc.x += v.x; acc.y += v.y; acc.z += v.z; acc.w += v.w;
    }
    ((float4*)dst)[(size_t)w * 32 + lane] = acc;
}

__global__ void k_agg(const float* __restrict__ src, float* __restrict__ dst,
                      const int* __restrict__ rp, const int* __restrict__ adj, int n,
                      const float* __restrict__ st, const float* __restrict__ gg,
                      const float* __restrict__ bb, int cnt) {
    int w    = (blockIdx.x * blockDim.x + threadIdx.x) >> 5;
    int lane = threadIdx.x & 31;
    if (w >= n) return;
    bool tf = (st != nullptr);
    float4 sc = make_float4(1.f, 1.f, 1.f, 1.f), sh = make_float4(0.f, 0.f, 0.f, 0.f);
    if (tf) {
        float inv = 1.f / (float)cnt;
        int c = lane * 4;
        bnparam(st, gg, bb, inv, c + 0, sc.x, sh.x);
        bnparam(st, gg, bb, inv, c + 1, sc.y, sh.y);
        bnparam(st, gg, bb, inv, c + 2, sc.z, sh.z);
        bnparam(st, gg, bb, inv, c + 3, sc.w, sh.w);
    }
    const float4* s4 = (const float4*)src;
    float4 acc = xf4(s4[(size_t)w * 32 + lane], sc, sh, tf);
    int s = rp[w], e = rp[w + 1];
    int i = s;
    for (; i + 4 <= e; i += 4) {
        int u0 = adj[i], u1 = adj[i + 1], u2 = adj[i + 2], u3 = adj[i + 3];
        float4 v0 = __ldg(&s4[(size_t)u0 * 32 + lane]);
        float4 v1 = __ldg(&s4[(size_t)u1 * 32 + lane]);
        float4 v2 = __ldg(&s4[(size_t)u2 * 32 + lane]);
        float4 v3 = __ldg(&s4[(size_t)u3 * 32 + lane]);
        v0 = xf4(v0, sc, sh, tf); v1 = xf4(v1, sc, sh, tf);
        v2 = xf4(v2, sc, sh, tf); v3 = xf4(v3, sc, sh, tf);
        acc.x += v0.x + v1.x + v2.x + v3.x;
        acc.y += v0.y + v1.y + v2.y + v3.y;
        acc.z += v0.z + v1.z + v2.z + v3.z;
        acc.w += v0.w + v1.w + v2.w + v3.w;
    }
    for (; i < e; i++) {
        int u = adj[i];
        float4 v = xf4(__ldg(&s4[(size_t)u * 32 + lane]), sc, sh, tf);
        acc.x += v.x; acc.y += v.y; acc.z += v.z; acc.w += v.w;
    }
    ((float4*)dst)[(size_t)w * 32 + lane] = acc;
}

__global__ void k_subagg(const float* __restrict__ src, float* __restrict__ dst,
                         const int* __restrict__ sub, const int* __restrict__ cntp,
                         const float* __restrict__ st, const float* __restrict__ gg,
                         const float* __restrict__ bb, int cnt) {
    int nwarps = (gridDim.x * blockDim.x) >> 5;
    int w0     = (blockIdx.x * blockDim.x + threadIdx.x) >> 5;
    int lane   = threadIdx.x & 31;
    bool tf = (st != nullptr);
    float4 sc = make_float4(1.f, 1.f, 1.f, 1.f), sh = make_float4(0.f, 0.f, 0.f, 0.f);
    if (tf) {
        float inv = 1.f / (float)cnt;
        int c = lane * 4;
        bnparam(st, gg, bb, inv, c + 0, sc.x, sh.x);
        bnparam(st, gg, bb, inv, c + 1, sc.y, sh.y);
        bnparam(st, gg, bb, inv, c + 2, sc.z, sh.z);
        bnparam(st, gg, bb, inv, c + 3, sc.w, sh.w);
    }
    int c = *cntp;
    for (int e = w0; e < c; e += nwarps) {
        int s = sub[2 * e], d = sub[2 * e + 1];
        float4 v = xf4(((const float4*)src)[(size_t)s * 32 + lane], sc, sh, tf);
        float* tp = dst + (size_t)d * 128 + lane * 4;
        atomicAdd(tp + 0, v.x);
        atomicAdd(tp + 1, v.y);
        atomicAdd(tp + 2, v.z);
        atomicAdd(tp + 3, v.w);
    }
}

// ---------------- tensor-core GEMM (bf16 3-term split, pre-split W) ----------------
// 128-row tiles; single As buffer + register prefetch, 2 CTAs/SM.
// smem: As [128][12] uint4 = 24576B; Wh/Wl 4224 uint2 = 33792B each;
// bn + stats = 2048B. total = 94208B.
#define GEMM_SMEM_BYTES 94208

__global__ __launch_bounds__(256, 2) void k_gemm_tc(
    const float* __restrict__ A, const uint2* __restrict__ Wsp, float* __restrict__ C,
    int n, const float* __restrict__ stats_in, const float* __restrict__ gg,
    const float* __restrict__ bb, int cnt, float* __restrict__ stats_out) {
    extern __shared__ uint32_t sm[];
    uint4* As   = (uint4*)sm;                          // [128][12]
    uint2* Wh   = (uint2*)((char*)sm + 24576);         // [4224]
    uint2* Wl   = (uint2*)((char*)sm + 58368);
    float* bnsc = (float*)((char*)sm + 92160);
    float* bnsh = bnsc + 128;
    float* ssum = bnsh + 128;
    float* ssq  = ssum + 128;

    int tid = threadIdx.x;
    int r0  = blockIdx.x * 128;
    bool tf = (stats_in != nullptr);

    // ---- stage pre-split W: straight copy, no FP ----
    const uint4* wg = (const uint4*)Wsp;               // hi then lo, 2112 uint4 each
    uint4* whs = (uint4*)Wh;
    uint4* wls = (uint4*)Wl;
    #pragma unroll
    for (int i = 0; i < 9; i++) {
        int idx = i * 256 + tid;
        if (idx < 2112) {
            whs[idx] = wg[idx];
            wls[idx] = wg[2112 + idx];
        }
    }
    if (tid < 128) {
        float s = 1.f, sh = 0.f;
        if (tf) {
            float inv = 1.f / (float)cnt;
            bnparam(stats_in, gg, bb, inv, tid, s, sh);
        }
        bnsc[tid] = s; bnsh[tid] = sh;
        ssum[tid] = 0.f; ssq[tid] = 0.f;
    }
    __syncthreads();

    int warp = tid >> 5, lane = tid & 31, g = lane >> 2, kq = lane & 3;
    int srow = tid >> 3, sq = tid & 7;
    int sktgl = sq >> 2, skqs = sq & 3;

    float2 va[4], vb[4];

    auto loadch = [&](int ch) {
        int kbase = ch * 32 + sktgl * 16 + skqs * 2;
        #pragma unroll
        for (int i = 0; i < 4; i++) {
            int gr = r0 + i * 32 + srow;
            if (gr < n) {
                va[i] = *(const float2*)(A + (size_t)gr * 128 + kbase);
                vb[i] = *(const float2*)(A + (size_t)gr * 128 + kbase + 8);
            } else {
                va[i] = make_float2(0.f, 0.f);
                vb[i] = make_float2(0.f, 0.f);
            }
        }
    };
    auto storech = [&](int ch) {
        int kbase = ch * 32 + sktgl * 16 + skqs * 2;
        float sc0 = bnsc[kbase + 0], sh0 = bnsh[kbase + 0];
        float sc1 = bnsc[kbase + 1], sh1 = bnsh[kbase + 1];
        float sc8 = bnsc[kbase + 8], sh8 = bnsh[kbase + 8];
        float sc9 = bnsc[kbase + 9], sh9 = bnsh[kbase + 9];
        #pragma unroll
        for (int i = 0; i < 4; i++) {
            int row = i * 32 + srow;
            float2 a = va[i], b = vb[i];
            if (tf) {
                a.x = fmaxf(fmaf(a.x, sc0, sh0), 0.f);
                a.y = fmaxf(fmaf(a.y, sc1, sh1), 0.f);
                b.x = fmaxf(fmaf(b.x, sc8, sh8), 0.f);
                b.y = fmaxf(fmaf(b.y, sc9, sh9), 0.f);
            }
            uint32_t ha, la, hb, lb;
            split2(a.x, a.y, ha, la);
            split2(b.x, b.y, hb, lb);
            As[row * 12 + sq] = make_uint4(ha, hb, la, lb);
        }
    };

    float acc[16][4];
    #pragma unroll
    for (int nt = 0; nt < 16; nt++)
        #pragma unroll
        for (int j = 0; j < 4; j++) acc[nt][j] = 0.f;

    loadch(0);
    storech(0);
    __syncthreads();

    for (int ch = 0; ch < 4; ch++) {
        if (ch < 3) loadch(ch + 1);
        #pragma unroll
        for (int ktgl = 0; ktgl < 2; ktgl++) {
            int q0 = ktgl * 4 + kq;
            int arow = warp * 16 + g;
            uint4 A0 = As[(arow)     * 12 + q0];
            uint4 A1 = As[(arow + 8) * 12 + q0];
            int ktgG = ch * 2 + ktgl;
            const uint2* whp = Wh + (ktgG * 4 + kq) * 132;
            const uint2* wlp = Wl + (ktgG * 4 + kq) * 132;
            #pragma unroll
            for (int nt = 0; nt < 16; nt++) {
                int nn = nt * 8 + g;
                uint2 bh = whp[nn];
                uint2 bl = wlp[nn];
                mma_bf16(acc[nt], A0.x, A1.x, A0.y, A1.y, bh.x, bh.y);
                mma_bf16(acc[nt], A0.z, A1.z, A0.w, A1.w, bh.x, bh.y);
                mma_bf16(acc[nt], A0.x, A1.x, A0.y, A1.y, bl.x, bl.y);
            }
        }
        __syncthreads();
        if (ch < 3) {
            storech(ch + 1);
            __syncthreads();
        }
    }

    int rA = r0 + warp * 16 + g;
    int rB = rA + 8;
    bool okA = rA < n, okB = rB < n;
    #pragma unroll
    for (int nt = 0; nt < 16; nt++) {
        float* a = acc[nt];
        int col = nt * 8 + kq * 2;
        if (okA) *(float2*)(C + (size_t)rA * 128 + col) = make_float2(a[0], a[1]);
        if (okB) *(float2*)(C + (size_t)rB * 128 + col) = make_float2(a[2], a[3]);
    }
    #pragma unroll
    for (int nt = 0; nt < 16; nt++) {
        float* a = acc[nt];
        float s0 = 0.f, s1 = 0.f, q0 = 0.f, q1 = 0.f;
        if (okA) { s0 += a[0]; q0 += a[0] * a[0]; s1 += a[1]; q1 += a[1] * a[1]; }
        if (okB) { s0 += a[2]; q0 += a[2] * a[2]; s1 += a[3]; q1 += a[3] * a[3]; }
        #pragma unroll
        for (int o = 4; o < 32; o <<= 1) {
            s0 += __shfl_xor_sync(0xFFFFFFFFu, s0, o);
            s1 += __shfl_xor_sync(0xFFFFFFFFu, s1, o);
            q0 += __shfl_xor_sync(0xFFFFFFFFu, q0, o);
            q1 += __shfl_xor_sync(0xFFFFFFFFu, q1, o);
        }
        if (lane < 4) {
            int col = nt * 8 + lane * 2;
            atomicAdd(&ssum[col],     s0);
            atomicAdd(&ssum[col + 1], s1);
            atomicAdd(&ssq[col],      q0);
            atomicAdd(&ssq[col + 1],  q1);
        }
    }
    __syncthreads();
    if (tid < 128) {
        atomicAdd(&stats_out[tid],       ssum[tid]);
        atomicAdd(&stats_out[128 + tid], ssq[tid]);
    }
}

// ---------------- loss ----------------
__global__ void k_loss(const float* __restrict__ zon, const float* __restrict__ ztg,
                       const int* __restrict__ mn, int m,
                       const float* __restrict__ stO, const float* __restrict__ gO,
                       const float* __restrict__ bO, int cntO,
                       const float* __restrict__ stT, const float* __restrict__ gT,
                       const float* __restrict__ bT, int cntT,
                       float* __restrict__ out) {
    int gw   = (blockIdx.x * blockDim.x + threadIdx.x) >> 5;
    int lane = threadIdx.x & 31;
    __shared__ float ps[8];
    float val = 0.f;
    if (gw < m) {
        int c = lane * 4;
        float invO = 1.f / (float)cntO, invT = 1.f / (float)cntT;
        float4 scO, shO, scT, shT;
        bnparam(stO, gO, bO, invO, c + 0, scO.x, shO.x);
        bnparam(stO, gO, bO, invO, c + 1, scO.y, shO.y);
        bnparam(stO, gO, bO, invO, c + 2, scO.z, shO.z);
        bnparam(stO, gO, bO, invO, c + 3, scO.w, shO.w);
        bnparam(stT, gT, bT, invT, c + 0, scT.x, shT.x);
        bnparam(stT, gT, bT, invT, c + 1, scT.y, shT.y);
        bnparam(stT, gT, bT, invT, c + 2, scT.z, shT.z);
        bnparam(stT, gT, bT, invT, c + 3, scT.w, shT.w);
        int r = mn[gw];
        float4 x = ((const float4*)zon)[(size_t)r * 32 + lane];
        x = xf4(x, scO, shO, true);
        float4 y = ((const float4*)ztg)[(size_t)gw * 32 + lane];
        y = xf4(y, scT, shT, true);
        float dot = x.x * y.x + x.y * y.y + x.z * y.z + x.w * y.w;
        float nx  = x.x * x.x + x.y * x.y + x.z * x.z + x.w * x.w;
        float ny  = y.x * y.x + y.y * y.y + y.z * y.z + y.w * y.w;
        #pragma unroll
        for (int off = 16; off > 0; off >>= 1) {
            dot += __shfl_xor_sync(0xFFFFFFFFu, dot, off);
            nx  += __shfl_xor_sync(0xFFFFFFFFu, nx,  off);
            ny  += __shfl_xor_sync(0xFFFFFFFFu, ny,  off);
        }
        if (lane == 0) {
            float den = fmaxf(sqrtf(nx), 1e-12f) * fmaxf(sqrtf(ny), 1e-12f);
            val = (1.f - dot / den) / (float)m;
        }
    }
    int w = threadIdx.x >> 5;
    if (lane == 0) ps[w] = val;
    __syncthreads();
    if (threadIdx.x == 0) {
        float s = 0.f;
        #pragma unroll
        for (int i = 0; i < 8; i++) s += ps[i];
        atomicAdd(out, s);
    }
}

// ---------------- host orchestration ----------------
extern "C" void kernel_launch(void* const* d_in, const int* in_sizes, int n_in,
                              void* d_out, int out_size) {
    const float* feat  = (const float*)d_in[0];
    const float* token = (const float*)d_in[1];
    const int*   edge  = (const int*)d_in[2];
    const int*   mn    = (const int*)d_in[3];
    const float* onW1 = (const float*)d_in[4];
    const float* onW2 = (const float*)d_in[5];
    const float* ong1 = (const float*)d_in[6];
    const float* onb1 = (const float*)d_in[7];
    const float* ong2 = (const float*)d_in[8];
    const float* onb2 = (const float*)d_in[9];
    const float* tgW1 = (const float*)d_in[10];
    const float* tgW2 = (const float*)d_in[11];
    const float* tgg1 = (const float*)d_in[12];
    const float* tgb1 = (const float*)d_in[13];
    const float* tgg2 = (const float*)d_in[14];
    const float* tgb2 = (const float*)d_in[15];

    const int N = in_sizes[0] / DD;
    const int E = in_sizes[2] / 2;
    const int M = in_sizes[3];
    const int* srcp = edge;
    const int* dstp = edge + E;

    float *p_t, *p_z, *p_h2, *p_t2, *p_z2;
    int *p_rp, *p_cur, *p_adj, *p_mask, *p_map, *p_sub, *p_cnt, *p_bsum;
    float* p_stats;
    uint2* p_wsp;
    cudaGetSymbolAddress((void**)&p_t, g_t);
    cudaGetSymbolAddress((void**)&p_z, g_z);
    cudaGetSymbolAddress((void**)&p_h2, g_h2);
    cudaGetSymbolAddress((void**)&p_t2, g_t2);
    cudaGetSymbolAddress((void**)&p_z2, g_z2);
    cudaGetSymbolAddress((void**)&p_rp, g_rp);
    cudaGetSymbolAddress((void**)&p_cur, g_cur);
    cudaGetSymbolAddress((void**)&p_adj, g_adj);
    cudaGetSymbolAddress((void**)&p_mask, g_mask);
    cudaGetSymbolAddress((void**)&p_map, g_map);
    cudaGetSymbolAddress((void**)&p_sub, g_sub);
    cudaGetSymbolAddress((void**)&p_cnt, g_cnt);
    cudaGetSymbolAddress((void**)&p_bsum, g_bsum);
    cudaGetSymbolAddress((void**)&p_stats, g_stats);
    cudaGetSymbolAddress((void**)&p_wsp, g_wsplit);

    static cudaStream_t s1 = nullptr, s2 = nullptr;
    static cudaEvent_t evRoot = nullptr, evFork = nullptr, evJoin = nullptr, evW = nullptr;
    static bool init_done = false;
    if (!init_done) {
        cudaFuncSetAttribute(k_gemm_tc, cudaFuncAttributeMaxDynamicSharedMemorySize,
                             GEMM_SMEM_BYTES);
        cudaStreamCreateWithFlags(&s1, cudaStreamNonBlocking);
        cudaStreamCreateWithFlags(&s2, cudaStreamNonBlocking);
        cudaEventCreateWithFlags(&evRoot, cudaEventDisableTiming);
        cudaEventCreateWithFlags(&evFork, cudaEventDisableTiming);
        cudaEventCreateWithFlags(&evJoin, cudaEventDisableTiming);
        cudaEventCreateWithFlags(&evW, cudaEventDisableTiming);
        init_done = true;
    }

    cudaStream_t st = 0;
    const int TB = 256;
    const int n4N = N * 32, n4M = M * 32;

    float* S0 = p_stats + 0 * 256;
    float* S1 = p_stats + 1 * 256;
    float* S2 = p_stats + 2 * 256;
    float* S3 = p_stats + 3 * 256;
    float* S4 = p_stats + 4 * 256;
    float* S5 = p_stats + 5 * 256;
    float* S6 = p_stats + 6 * 256;
    float* S7 = p_stats + 7 * 256;

    uint2* Won1a = p_wsp + 0 * 2 * WSP_WORDS;
    uint2* Won1b = p_wsp + 1 * 2 * WSP_WORDS;
    uint2* Won2a = p_wsp + 2 * 2 * WSP_WORDS;
    uint2* Won2b = p_wsp + 3 * 2 * WSP_WORDS;
    uint2* Wtg1a = p_wsp + 4 * 2 * WSP_WORDS;
    uint2* Wtg1b = p_wsp + 5 * 2 * WSP_WORDS;
    uint2* Wtg2a = p_wsp + 6 * 2 * WSP_WORDS;
    uint2* Wtg2b = p_wsp + 7 * 2 * WSP_WORDS;

    const int gN = (N + 127) / 128, gM = (M + 127) / 128;
    const int nb = (N + 4095) / 4096;

    // ---- capture-legal fork: root event on origin stream FIRST ----
    cudaEventRecord(evRoot, st);
    cudaStreamWaitEvent(s2, evRoot, 0);
    cudaStreamWaitEvent(s1, evRoot, 0);

    // ---- weight pre-split on s2 (overlaps setup) ----
    k_splitW<<<8, 256, 0, s2>>>(onW1, onW1 + DD * DD, onW2, onW2 + DD * DD,
                                tgW1, tgW1 + DD * DD, tgW2, tgW2 + DD * DD, p_wsp);
    cudaEventRecord(evW, s2);

    // ---- target-path input prep on s1 (reads only inputs) ----
    k_gatherfeat<<<(n4M + TB - 1) / TB, TB, 0, s1>>>(feat, mn, p_h2, n4M);
    k_copyT<<<(n4M + TB - 1) / TB, TB, 0, s1>>>(p_h2, p_t2, n4M,
                                                nullptr, nullptr, nullptr, 0);

    // ---- setup on st ----
    k_init<<<(N + TB - 1) / TB, TB, 0, st>>>(p_mask, p_cur, p_cnt, p_stats,
                                             (float*)d_out, N);
    k_buildmaps<<<(M + TB - 1) / TB, TB, 0, st>>>(mn, p_mask, p_map, M);
    k_deg_sub<<<(E + TB - 1) / TB, TB, 0, st>>>(srcp, dstp, p_mask, p_map,
                                                p_cur, p_sub, p_cnt, E);
    cudaEventRecord(evFork, st);

    // ---- online encoder chain on st ----
    k_scanA<<<nb, 1024, 0, st>>>(p_cur, p_rp, p_bsum, N);
    k_scanC<<<((N + 3) / 4 + TB - 1) / TB, TB, 0, st>>>(p_bsum, p_rp, p_cur, N, nb);
    k_fill<<<(E + TB - 1) / TB, TB, 0, st>>>(srcp, dstp, p_cur, p_adj, E);
    k_agg_m<<<(n4N + TB - 1) / TB, TB, 0, st>>>(feat, token, p_mask, p_t,
                                                p_rp, p_adj, N);
    cudaStreamWaitEvent(st, evW, 0);
    k_gemm_tc<<<gN, 256, GEMM_SMEM_BYTES, st>>>(p_t, Won1a, p_z, N,
                                                nullptr, nullptr, nullptr, 0, S0);
    k_gemm_tc<<<gN, 256, GEMM_SMEM_BYTES, st>>>(p_z, Won2a, p_z, N,
                                                S0, ong1, onb1, N, S1);
    k_agg<<<(n4N + TB - 1) / TB, TB, 0, st>>>(p_z, p_t, p_rp, p_adj, N,
                                              S1, ong2, onb2, N);
    k_gemm_tc<<<gN, 256, GEMM_SMEM_BYTES, st>>>(p_t, Won1b, p_z, N,
                                                nullptr, nullptr, nullptr, 0, S2);
    k_gemm_tc<<<gN, 256, GEMM_SMEM_BYTES, st>>>(p_z, Won2b, p_z, N,
                                                S2, ong1 + DD, onb1 + DD, N, S3);

    // ---- target encoder (induced subgraph) on s1, overlapped ----
    cudaStreamWaitEvent(s1, evFork, 0);
    cudaStreamWaitEvent(s1, evW, 0);
    k_subagg<<<64, 256, 0, s1>>>(p_h2, p_t2, p_sub, p_cnt,
                                 nullptr, nullptr, nullptr, 0);
    k_gemm_tc<<<gM, 256, GEMM_SMEM_BYTES, s1>>>(p_t2, Wtg1a, p_z2, M,
                                                nullptr, nullptr, nullptr, 0, S4);
    k_gemm_tc<<<gM, 256, GEMM_SMEM_BYTES, s1>>>(p_z2, Wtg2a, p_z2, M,
                                                S4, tgg1, tgb1, M, S5);
    k_copyT<<<(n4M + TB - 1) / TB, TB, 0, s1>>>(p_z2, p_t2, n4M,
                                                S5, tgg2, tgb2, M);
    k_subagg<<<64, 256, 0, s1>>>(p_z2, p_t2, p_sub, p_cnt,
                                 S5, tgg2, tgb2, M);
    k_gemm_tc<<<gM, 256, GEMM_SMEM_BYTES, s1>>>(p_t2, Wtg1b, p_z2, M,
                                                nullptr, nullptr, nullptr, 0, S6);
    k_gemm_tc<<<gM, 256, GEMM_SMEM_BYTES, s1>>>(p_z2, Wtg2b, p_z2, M,
                                                S6, tgg1 + DD, tgb1 + DD, M, S7);
    cudaEventRecord(evJoin, s1);

    // ---- join + loss ----
    cudaStreamWaitEvent(st, evJoin, 0);
    k_loss<<<(M * 32 + TB - 1) / TB, TB, 0, st>>>(p_z, p_z2, mn, M,
                                                  S3, ong2 + DD, onb2 + DD, N,
                                                  S7, tgg2 + DD, tgb2 + DD, M,
                                                  (float*)d_out);
}